// round 15
// baseline (speedup 1.0000x reference)
#include <cuda_runtime.h>

#define BB 64
#define CC 512
#define TT 16
#define HWD 196
#define KK 8
#define CPB 2                      // slabs per unit (both roles)
#define BCHUNK 8                   // batches per chunk (51MB)
#define NCHUNK (BB / BCHUNK)       // 8
#define UNITS ((BCHUNK * CC) / CPB)  // 2048 per chunk per role

// [b][t][c] per-channel partial scores
__device__ float    g_partial[BB * TT * CC];
// [b][t] -> output slot (0-7 = approx pos, 8-15 = 8+detail pos)
__device__ int      g_dest[BB * TT];
// per-batch pool completion (exactly 256 adds per launch -> modulo-safe)
__device__ unsigned g_pcnt[BB];

// ---------------------------------------------------------------------------
// One pipeline step. Even blocks: pool a unit of chunk b0p (strip loader +
// partial scores; last block of each batch computes scores + dest slots,
// single-fence publish). Odd blocks: gather a unit of chunk b0g, whose dest
// was produced by the PREVIOUS launch (stream order = dependency; no spins).
// Gather reads hit L2 (chunk loaded by previous launch still resident).
// ---------------------------------------------------------------------------
__global__ __launch_bounds__(256) void k_step(const float* __restrict__ x,
                                              float* __restrict__ out,
                                              int b0p, int b0g, int mixed) {
    __shared__ float pooled[CPB * TT * 49];   // 1568
    __shared__ float sc[CPB * 49];            // 98
    __shared__ float v[TT];
    __shared__ int   fa[TT], fd[TT], dst_slot[TT];
    __shared__ int   sm_sel;

    int unit, is_pool;
    if (mixed) { is_pool = !(blockIdx.x & 1); unit = blockIdx.x >> 1; }
    else       { is_pool = (b0p >= 0);        unit = blockIdx.x; }

    if (is_pool) {
        // ============================ pool unit ============================
        const int bc0 = b0p * CC + unit * CPB;
        const int b   = bc0 >> 9;
        const float* __restrict__ base = x + (size_t)bc0 * (TT * HWD);

        if (threadIdx.x < CPB * TT * 7) {     // 224 strips, 7 indep LDG.128
            int s  = threadIdx.x;
            int ch = s / 112;
            int q  = s - ch * 112;
            int t  = q / 7;
            int y  = q - t * 7;               // pool row (input rows 2y,2y+1)
            const float4* __restrict__ sp =
                (const float4*)(base + (ch * TT + t) * HWD + y * 28);
            float4 r0 = sp[0], r1 = sp[1], r2 = sp[2], r3 = sp[3];
            float4 r4 = sp[4], r5 = sp[5], r6 = sp[6];
            float* d = pooled + (ch * TT + t) * 49 + y * 7;
            d[0] = 0.25f * (r0.x + r0.y + r3.z + r3.w);
            d[1] = 0.25f * (r0.z + r0.w + r4.x + r4.y);
            d[2] = 0.25f * (r1.x + r1.y + r4.z + r4.w);
            d[3] = 0.25f * (r1.z + r1.w + r5.x + r5.y);
            d[4] = 0.25f * (r2.x + r2.y + r5.z + r5.w);
            d[5] = 0.25f * (r2.z + r2.w + r6.x + r6.y);
            d[6] = 0.25f * (r3.x + r3.y + r6.z + r6.w);
        }
        __syncthreads();

        if (threadIdx.x < CPB * 49) {         // 98 column sums
            int ch = threadIdx.x / 49, blk = threadIdx.x - ch * 49;
            const float* pc = pooled + ch * (TT * 49) + blk;
            float s = 0.f;
            #pragma unroll
            for (int t = 0; t < TT; t++) s += pc[t * 49];
            sc[threadIdx.x] = s;
        }
        __syncthreads();

        {
            const int ch = threadIdx.x >> 7;
            const int t  = (threadIdx.x >> 3) & 15;
            const int g  = threadIdx.x & 7;
            const float* pr = pooled + ch * (TT * 49) + t * 49;
            const float* sr = sc + ch * 49;
            float acc = 0.f;
            #pragma unroll
            for (int blk = g; blk < 49; blk += 8)
                acc += pr[blk] * sr[blk];
            acc += __shfl_xor_sync(0xffffffffu, acc, 4);
            acc += __shfl_xor_sync(0xffffffffu, acc, 2);
            acc += __shfl_xor_sync(0xffffffffu, acc, 1);
            if (g == 0) {
                int bc = bc0 + ch;
                g_partial[(b * TT + t) * CC + (bc & (CC - 1))] = acc;
            }
        }
        __syncthreads();                      // block's partial stores done

        if (threadIdx.x == 0) {               // single-fence publish
            __threadfence();
            unsigned pc = atomicAdd(&g_pcnt[b], 1u);
            sm_sel = ((pc & 255u) == 255u);   // last of 256 this launch
        }
        __syncthreads();
        if (!sm_sel) return;
        __threadfence();                      // see all batch partials

        {
            int t = threadIdx.x >> 4, g = threadIdx.x & 15;
            const float* __restrict__ pp = g_partial + (b * TT + t) * CC;
            float s = 0.f;
            #pragma unroll
            for (int j = 0; j < CC / 16; j++) s += __ldcg(&pp[g + 16 * j]);
            s += __shfl_xor_sync(0xffffffffu, s, 8);
            s += __shfl_xor_sync(0xffffffffu, s, 4);
            s += __shfl_xor_sync(0xffffffffu, s, 2);
            s += __shfl_xor_sync(0xffffffffu, s, 1);
            if (g == 0)
                v[t] = s * (1.0f / (float)(CC * TT)) + ((t & 1) == 0 ? 1.0f : 0.0f);
        }
        __syncthreads();
        if (threadIdx.x < TT) {               // jax top_k tie semantics
            const int i = threadIdx.x;
            const float mv = v[i];
            int ra = 0, rd = 0;
            #pragma unroll
            for (int j = 0; j < TT; j++) {
                float vj = v[j];
                ra += (vj > mv) || (vj == mv && j < i);
                rd += (vj < mv) || (vj == mv && j < i);
            }
            fa[i] = (ra < KK);
            fd[i] = (rd < KK);
        }
        __syncthreads();
        if (threadIdx.x < TT) {
            const int i = threadIdx.x;
            int pa = 0, pd = 0;
            for (int j = 0; j < i; j++) { pa += fa[j]; pd += fd[j]; }
            // ranks form a permutation (ra+rd==15): exactly one of fa/fd set
            g_dest[b * TT + i] = fa[i] ? pa : (KK + pd);
        }
    } else {
        // =========================== gather unit ===========================
        const int bc0 = b0g * CC + unit * CPB;
        const int b   = bc0 >> 9;
        if (threadIdx.x < TT)
            dst_slot[threadIdx.x] = __ldcg(&g_dest[b * TT + threadIdx.x]);
        __syncthreads();

        const float4* __restrict__ src4 = (const float4*)x;
        float4* __restrict__ out4 = (float4*)out;
        const int c = bc0 & (CC - 1);

        #pragma unroll 7
        for (int i = threadIdx.x; i < CPB * TT * 49; i += 256) {
            int cl  = i / 784;
            int r   = i - cl * 784;
            int t   = r / 49;
            int hw4 = r - t * 49;
            float4 val = __ldcs(&src4[(size_t)bc0 * 784 + i]);   // L2-resident
            int s = dst_slot[t];
            unsigned half = (unsigned)s >> 3;
            unsigned j = (unsigned)s & (KK - 1);
            size_t o = (size_t)half * (BB * CC * KK * 49)
                     + ((size_t)(b * CC + c + cl) * KK + j) * 49 + hw4;
            __stcs(&out4[o], val);
        }
    }
}

// ---------------------------------------------------------------------------
extern "C" void kernel_launch(void* const* d_in, const int* in_sizes, int n_in,
                              void* d_out, int out_size) {
    const float* x = (const float*)d_in[0];
    float* out = (float*)d_out;

    // L0: pool chunk 0 only
    k_step<<<UNITS, 256>>>(x, out, 0, -1, 0);
    // L1..L7: pool chunk i + gather chunk i-1 (interleaved even/odd blocks)
    for (int i = 1; i < NCHUNK; i++)
        k_step<<<2 * UNITS, 256>>>(x, out, i * BCHUNK, (i - 1) * BCHUNK, 1);
    // L8: gather last chunk only
    k_step<<<UNITS, 256>>>(x, out, -1, (NCHUNK - 1) * BCHUNK, 0);
}

// round 16
// speedup vs baseline: 1.1286x; 1.1286x over previous
#include <cuda_runtime.h>

#define BB 64
#define CC 512
#define TT 16
#define HWD 196
#define KK 8
#define CPB 2                 // channels per pool block

// [b][t][c] per-channel partial scores
__device__ float g_partial[BB * TT * CC];
// [b][t] -> output slot 0..15 (0-7 = approx pos, 8-15 = 8+detail pos)
__device__ int   g_dest[BB * TT];

// ---------------------------------------------------------------------------
// Kernel 1 (R14, proven 68.6us): one block per 2 slabs, 256 threads.
// ---------------------------------------------------------------------------
__global__ __launch_bounds__(256) void k_pool(const float* __restrict__ x) {
    __shared__ float pooled[CPB * TT * 49];   // 1568
    __shared__ float sc[CPB * 49];            // 98

    const int bc0 = blockIdx.x * CPB;
    const float* __restrict__ base = x + (size_t)bc0 * (TT * HWD);

    const int p = threadIdx.x;
    if (p < CPB * TT * 7) {                   // 224 strips, 7 indep LDG.128
        int ch = p / 112;
        int q  = p - ch * 112;
        int t  = q / 7;
        int y  = q - t * 7;                   // pool row (input rows 2y,2y+1)
        const float4* __restrict__ src =
            (const float4*)(base + ch * (TT * HWD) + t * HWD + y * 28);
        float4 r0 = src[0], r1 = src[1], r2 = src[2], r3 = src[3];
        float4 r4 = src[4], r5 = src[5], r6 = src[6];
        float* dst = pooled + ch * (TT * 49) + t * 49 + y * 7;
        dst[0] = 0.25f * (r0.x + r0.y + r3.z + r3.w);
        dst[1] = 0.25f * (r0.z + r0.w + r4.x + r4.y);
        dst[2] = 0.25f * (r1.x + r1.y + r4.z + r4.w);
        dst[3] = 0.25f * (r1.z + r1.w + r5.x + r5.y);
        dst[4] = 0.25f * (r2.x + r2.y + r5.z + r5.w);
        dst[5] = 0.25f * (r2.z + r2.w + r6.x + r6.y);
        dst[6] = 0.25f * (r3.x + r3.y + r6.z + r6.w);
    }
    __syncthreads();

    if (threadIdx.x < CPB * 49) {
        int ch = threadIdx.x / 49, blk = threadIdx.x - ch * 49;
        const float* pc = pooled + ch * (TT * 49) + blk;
        float s = 0.f;
        #pragma unroll
        for (int t = 0; t < TT; t++) s += pc[t * 49];
        sc[threadIdx.x] = s;
    }
    __syncthreads();

    const int ch = threadIdx.x >> 7;
    const int t  = (threadIdx.x >> 3) & 15;
    const int g  = threadIdx.x & 7;
    const float* pr = pooled + ch * (TT * 49) + t * 49;
    const float* sr = sc + ch * 49;
    float acc = 0.f;
    #pragma unroll
    for (int blk = g; blk < 49; blk += 8)
        acc += pr[blk] * sr[blk];
    acc += __shfl_xor_sync(0xffffffffu, acc, 4);
    acc += __shfl_xor_sync(0xffffffffu, acc, 2);
    acc += __shfl_xor_sync(0xffffffffu, acc, 1);
    if (g == 0) {
        int bc = bc0 + ch;
        int b = bc >> 9, c = bc & (CC - 1);
        g_partial[(b * TT + t) * CC + c] = acc;
    }
}

// ---------------------------------------------------------------------------
// Kernel 2 (proven ~3us): fused channel-reduce + selection, block per b.
// ---------------------------------------------------------------------------
__global__ __launch_bounds__(256) void k_score_select() {
    __shared__ float v[TT];
    __shared__ int fa[TT], fd[TT];
    const int b = blockIdx.x;
    const int t = threadIdx.x >> 4;
    const int g = threadIdx.x & 15;

    const float* __restrict__ p = g_partial + (b * TT + t) * CC;
    float s = 0.f;
    #pragma unroll
    for (int j = 0; j < CC / 16; j++) s += p[g + 16 * j];
    s += __shfl_xor_sync(0xffffffffu, s, 8);
    s += __shfl_xor_sync(0xffffffffu, s, 4);
    s += __shfl_xor_sync(0xffffffffu, s, 2);
    s += __shfl_xor_sync(0xffffffffu, s, 1);
    if (g == 0)
        v[t] = s * (1.0f / (float)(CC * TT)) + ((t & 1) == 0 ? 1.0f : 0.0f);
    __syncthreads();

    if (threadIdx.x < TT) {                   // jax top_k tie semantics
        const int i = threadIdx.x;
        const float mv = v[i];
        int ra = 0, rd = 0;
        #pragma unroll
        for (int j = 0; j < TT; j++) {
            ra += (v[j] > mv) || (v[j] == mv && j < i);
            rd += (v[j] < mv) || (v[j] == mv && j < i);
        }
        fa[i] = (ra < KK);
        fd[i] = (rd < KK);
    }
    __syncthreads();
    if (threadIdx.x < TT) {
        const int i = threadIdx.x;
        int pa = 0, pd = 0;
        for (int j = 0; j < i; j++) { pa += fa[j]; pd += fd[j]; }
        // ranks form a permutation (ra+rd==15): exactly one of fa/fd is set
        g_dest[b * TT + i] = fa[i] ? pa : (KK + pd);
    }
}

// ---------------------------------------------------------------------------
// Kernel 3: gather with 8 independent float4s per thread (~100KB in flight
// per SM), regions in DESCENDING order to consume the input lines k_pool
// left in L2 first. __ldcs: dead after read; __stcs: streaming output.
// ---------------------------------------------------------------------------
#define TOTAL4   (BB * CC * TT * (HWD / 4))   // 25,690,112 float4s
#define G_MLP    8
#define G_BLOCKS (TOTAL4 / (G_MLP * 256))     // 12544

__global__ __launch_bounds__(256) void k_gather(const float* __restrict__ x,
                                                float* __restrict__ out) {
    const float4* __restrict__ src4 = (const float4*)x;
    float4* __restrict__ out4 = (float4*)out;

    // descending region order: early blocks hit the L2-resident tail
    const unsigned base =
        (unsigned)(G_BLOCKS - 1 - blockIdx.x) * (G_MLP * 256u) + threadIdx.x;

    float4 val[G_MLP];
    #pragma unroll
    for (int k = 0; k < G_MLP; k++)
        val[k] = __ldcs(&src4[base + (unsigned)k * 256u]);   // 8 indep loads

    #pragma unroll
    for (int k = 0; k < G_MLP; k++) {
        unsigned i = base + (unsigned)k * 256u;
        unsigned hw4 = i % 49u;
        unsigned r = i / 49u;
        unsigned t = r & (TT - 1);
        unsigned c = (r >> 4) & (CC - 1);
        unsigned b = r >> 13;
        int s = __ldg(&g_dest[b * TT + t]);
        unsigned half = (unsigned)s >> 3;
        unsigned j = (unsigned)s & (KK - 1);
        unsigned o = half * (BB * CC * KK * 49u)
                   + ((b * CC + c) * KK + j) * 49u + hw4;
        __stcs(&out4[o], val[k]);
    }
}

// ---------------------------------------------------------------------------
extern "C" void kernel_launch(void* const* d_in, const int* in_sizes, int n_in,
                              void* d_out, int out_size) {
    const float* x = (const float*)d_in[0];
    float* out = (float*)d_out;

    k_pool<<<(BB * CC) / CPB, 256>>>(x);
    k_score_select<<<BB, 256>>>();
    k_gather<<<G_BLOCKS, 256>>>(x, out);
}